// round 17
// baseline (speedup 1.0000x reference)
#include <cuda_runtime.h>
#include <cuda_bf16.h>

// Contrastive loss v14 = v3 loop body VERBATIM (measured best 16.45us),
// launch changed 1024 -> 1036 blocks (148 SMs x exactly 7 resident blocks).
// v3's 1024 blocks split 136 SMs @7 / 12 SMs @6 -> the 12 light SMs idle
// for the final ~1/7 of the kernel. 1036 equalizes per-SM block count at
// UNCHANGED occupancy (regs=32 allows 8/SM; we place 7). Zero loop-body
// change, zero register risk.
//
//   per pair p: sq = ||emb[a]-emb[b]||^2 ; d = sqrt(max(sq,1e-12))
//   loss_p = (1-i)*max(0,1-d)^2 + i*d^2 ; out = sum / (P+1e-10)

#define D_DIM 512
#define VEC_PER_ROW (D_DIM / 4)      // 128 float4 per row
#define WARPS_PER_BLOCK 8
#define THREADS_PER_BLOCK (WARPS_PER_BLOCK * 32)
#define BLOCKS_BALANCED (148 * 7)    // 1036: exactly 7 blocks on every SM
#define MAX_BLOCKS 16384

__device__ float        g_partials[MAX_BLOCKS];
__device__ unsigned int g_counter = 0;

__device__ __forceinline__ unsigned int atom_add_acqrel(unsigned int* p,
                                                        unsigned int v) {
    unsigned int old;
    asm volatile("atom.acq_rel.gpu.global.add.u32 %0, [%1], %2;"
                 : "=r"(old) : "l"(p), "r"(v) : "memory");
    return old;
}

__global__ __launch_bounds__(THREADS_PER_BLOCK)
void contrastive_fused_kernel(const float* __restrict__ emb,
                              const int* __restrict__ pair_a,
                              const int* __restrict__ pair_b,
                              const int* __restrict__ pair_same,
                              float* __restrict__ out,
                              int P)
{
    const int warp_id     = threadIdx.x >> 5;
    const int lane        = threadIdx.x & 31;
    const int warp_global = blockIdx.x * WARPS_PER_BLOCK + warp_id;
    const int warp_stride = gridDim.x * WARPS_PER_BLOCK;

    const float4* __restrict__ embv = reinterpret_cast<const float4*>(emb);

    float warp_loss = 0.0f;   // meaningful on lane 0 only

    int p  = warp_global;
    int ia = 0, ib = 0;
    if (p < P) { ia = __ldg(pair_a + p); ib = __ldg(pair_b + p); }

    while (p < P) {
        // Prefetch next pair's indices (hides idx->row dependent chain).
        const int p_next = p + warp_stride;
        int ia_next = 0, ib_next = 0;
        if (p_next < P) {
            ia_next = __ldg(pair_a + p_next);
            ib_next = __ldg(pair_b + p_next);
        }

        const float4* __restrict__ ra = embv + (size_t)ia * VEC_PER_ROW;
        const float4* __restrict__ rb = embv + (size_t)ib * VEC_PER_ROW;

        // 8 independent 16B L2-only loads (512B/warp each, fully coalesced).
        float4 va[4], vb[4];
        #pragma unroll
        for (int k = 0; k < 4; ++k) {
            va[k] = __ldcg(ra + lane + k * 32);
            vb[k] = __ldcg(rb + lane + k * 32);
        }

        // ||a-b||^2 per lane.
        float s = 0.0f;
        #pragma unroll
        for (int k = 0; k < 4; ++k) {
            float dx = va[k].x - vb[k].x;
            float dy = va[k].y - vb[k].y;
            float dz = va[k].z - vb[k].z;
            float dw = va[k].w - vb[k].w;
            s += dx * dx + dy * dy + dz * dz + dw * dw;
        }

        // Warp tree reduction (5 shfl).
        #pragma unroll
        for (int off = 16; off > 0; off >>= 1)
            s += __shfl_xor_sync(0xFFFFFFFFu, s, off);

        if (lane == 0) {
            float sq = fmaxf(s, 1e-12f);
            float d = sqrtf(sq);
            float i = (float)__ldg(pair_same + p);
            float h = fmaxf(0.0f, 1.0f - d);
            warp_loss += (1.0f - i) * h * h + i * d * d;
        }

        p  = p_next;
        ia = ia_next;
        ib = ib_next;
    }

    // Block reduction of per-warp losses.
    __shared__ float s_loss[WARPS_PER_BLOCK];
    __shared__ bool  s_is_last;
    if (lane == 0) s_loss[warp_id] = warp_loss;
    __syncthreads();

    if (threadIdx.x == 0) {
        float acc = 0.0f;
        #pragma unroll
        for (int w = 0; w < WARPS_PER_BLOCK; ++w) acc += s_loss[w];
        g_partials[blockIdx.x] = acc;
        unsigned int prev = atom_add_acqrel(&g_counter, 1u);  // release-orders store
        s_is_last = (prev == gridDim.x - 1);
        if (s_is_last) atomicExch(&g_counter, 0u);  // replay-safe self-reset
    }
    __syncthreads();

    // Last block: deterministic final reduction in fixed index order.
    if (s_is_last) {
        __shared__ float s_fin[THREADS_PER_BLOCK];
        float acc = 0.0f;
        for (int i = threadIdx.x; i < (int)gridDim.x; i += THREADS_PER_BLOCK)
            acc += g_partials[i];
        s_fin[threadIdx.x] = acc;
        __syncthreads();
        #pragma unroll
        for (int off = THREADS_PER_BLOCK / 2; off > 0; off >>= 1) {
            if (threadIdx.x < off) s_fin[threadIdx.x] += s_fin[threadIdx.x + off];
            __syncthreads();
        }
        if (threadIdx.x == 0)
            out[0] = s_fin[0] / ((float)P + 1e-10f);
    }
}

extern "C" void kernel_launch(void* const* d_in, const int* in_sizes, int n_in,
                              void* d_out, int out_size)
{
    const float* emb       = (const float*)d_in[0];
    const int*   pair_a    = (const int*)d_in[1];
    const int*   pair_b    = (const int*)d_in[2];
    const int*   pair_same = (const int*)d_in[3];
    float*       out       = (float*)d_out;

    const int P = in_sizes[1];  // element count of pair_a

    // Balanced single wave: exactly 7 blocks on each of 148 SMs.
    int num_blocks = BLOCKS_BALANCED;
    int max_useful = (P + WARPS_PER_BLOCK - 1) / WARPS_PER_BLOCK;
    if (num_blocks > max_useful) num_blocks = max_useful;
    if (num_blocks < 1) num_blocks = 1;
    if (num_blocks > MAX_BLOCKS) num_blocks = MAX_BLOCKS;

    contrastive_fused_kernel<<<num_blocks, THREADS_PER_BLOCK>>>(
        emb, pair_a, pair_b, pair_same, out, P);
}